// round 10
// baseline (speedup 1.0000x reference)
#include <cuda_runtime.h>
#include <cstdint>

#define NUM_CLASSES 1024
#define FEAT_DIM    512
#define BATCH       16384
#define ALPHA       0.5f
#define MAXC        192    // slot capacity per class (Binomial mean 16; max ~40)
#define SLOTS       48     // rows per TMA chunk (covers n<=48 in one phase)
#define ROW_BYTES   2048   // one feature row
#define DSMEM_BYTES (1024 + SLOTS * ROW_BYTES)   // mbar pad + row buffer

// Scratch (allocation-free rule): zero-init at module load; cl_main re-zeros
// g_cnt in its epilogue so every graph replay sees zeros.
__device__ int g_cnt[NUM_CLASSES];
__device__ int g_slot[NUM_CLASSES * MAXC];

// Kernel 1: histogram + scatter sample indices into per-class slots.
__global__ __launch_bounds__(256) void cl_hist_scatter(const int* __restrict__ labels) {
    int i = blockIdx.x * blockDim.x + threadIdx.x;
    if (i < BATCH) {
        int c = labels[i];
        int p = atomicAdd(&g_cnt[c], 1);
        if (p < MAXC) g_slot[c * MAXC + p] = i;
    }
}

// Kernel 2: one block per class, 8 warps. Feature rows arrive via TMA bulk
// copies (cp.async.bulk, 2KB each) against one mbarrier — up to 48 copies
// (96KB) in flight per block with zero register cost. Warps compute from
// SMEM: warp w takes samples j = w + 8k, accumulates delta in registers,
// warp-shuffle reduces the squared distance. One combine at the end.
__global__ __launch_bounds__(256) void cl_main(
    const float*  __restrict__ feat,     // [BATCH*512]
    const float4* __restrict__ centers,  // [C][128] float4
    float*        __restrict__ result,   // [BATCH]
    float4*       __restrict__ newc)     // [C][128] float4
{
    extern __shared__ char dsm[];
    uint32_t smem_base;
    asm("{ .reg .u64 t0; cvta.to.shared.u64 t0, %1; cvt.u32.u64 %0, t0; }"
        : "=r"(smem_base) : "l"(dsm));
    const uint32_t mbar = smem_base;              // 8B, 8-aligned
    const uint32_t bufa = smem_base + 1024;       // TMA dst, 1024-aligned
    float4* bufv = (float4*)(dsm + 1024);         // same memory, compute view

    const int c    = blockIdx.x;
    const int t    = threadIdx.x;
    const int lane = t & 31;
    const int w    = t >> 5;

    const int cnt = g_cnt[c];
    const int n   = cnt < MAXC ? cnt : MAXC;

    if (t == 0)
        asm volatile("mbarrier.init.shared::cta.b64 [%0], %1;"
                     :: "r"(mbar), "r"(1) : "memory");
    __syncthreads();

    const float4* crow = centers + c * 128;
    float4 ctr[4];
    #pragma unroll
    for (int k = 0; k < 4; k++) ctr[k] = crow[lane + 32 * k];

    float4 dl[4];
    #pragma unroll
    for (int k = 0; k < 4; k++) dl[k] = make_float4(0.f, 0.f, 0.f, 0.f);

    const int* slot = g_slot + c * MAXC;

    int phase = 0;
    for (int cs = 0; cs < n; cs += SLOTS, phase ^= 1) {
        const int m = (n - cs) < SLOTS ? (n - cs) : SLOTS;

        // Every warp preloads this chunk's indices (lane k -> sample cs+k).
        int idx0 = (lane < m)      ? slot[cs + lane]      : 0;
        int idx1 = (32 + lane < m) ? slot[cs + 32 + lane] : 0;

        // Warp 0 issues the TMA gather: one bulk copy per sample row.
        if (w == 0) {
            if (lane == 0)
                asm volatile(
                    "mbarrier.arrive.expect_tx.shared::cta.b64 _, [%0], %1;"
                    :: "r"(mbar), "r"((unsigned)(m * ROW_BYTES)) : "memory");
            for (int j = 0; j < m; j++) {
                int b = (j < 32) ? __shfl_sync(0xffffffffu, idx0, j)
                                 : __shfl_sync(0xffffffffu, idx1, j - 32);
                if (lane == 0) {
                    const float* src = feat + (size_t)b * FEAT_DIM;
                    asm volatile(
                        "cp.async.bulk.shared::cta.global"
                        ".mbarrier::complete_tx::bytes [%0], [%1], %2, [%3];"
                        :: "r"(bufa + (unsigned)(j * ROW_BYTES)), "l"(src),
                           "r"((unsigned)ROW_BYTES), "r"(mbar) : "memory");
                }
            }
        }

        // Wait for all rows of this chunk (acquire: orders TMA writes
        // before our generic shared loads).
        asm volatile(
            "{ .reg .pred P;\n\t"
            "WL%=: mbarrier.try_wait.parity.acquire.cta.shared::cta.b64 P, [%0], %1, 0x989680;\n\t"
            "@P bra WD%=;\n\t"
            "bra WL%=;\n\t"
            "WD%=: }"
            :: "r"(mbar), "r"(phase) : "memory");

        // Warp w consumes samples j = w + 8k from SMEM.
        for (int j = w; j < m; j += 8) {
            const int b = (j < 32) ? __shfl_sync(0xffffffffu, idx0, j)
                                   : __shfl_sync(0xffffffffu, idx1, j - 32);
            float4 f[4];
            #pragma unroll
            for (int q = 0; q < 4; q++) f[q] = bufv[j * 128 + lane + 32 * q];

            float ss = 0.f;
            #pragma unroll
            for (int q = 0; q < 4; q++) {
                float4 d;
                d.x = ctr[q].x - f[q].x;
                d.y = ctr[q].y - f[q].y;
                d.z = ctr[q].z - f[q].z;
                d.w = ctr[q].w - f[q].w;
                dl[q].x += d.x; dl[q].y += d.y;
                dl[q].z += d.z; dl[q].w += d.w;
                ss += d.x * d.x + d.y * d.y + d.z * d.z + d.w * d.w;
            }
            #pragma unroll
            for (int o = 16; o; o >>= 1)
                ss += __shfl_xor_sync(0xffffffffu, ss, o);
            if (lane == 0) result[b] = ss;
        }
        __syncthreads();   // buffer safe to reuse / repurpose
    }

    // Cross-warp delta combine (buffer is idle now).
    #pragma unroll
    for (int k = 0; k < 4; k++) bufv[w * 128 + lane + 32 * k] = dl[k];
    __syncthreads();

    if (t < 128) {
        float4 dsum = bufv[t];
        #pragma unroll
        for (int ww = 1; ww < 8; ww++) {
            float4 v = bufv[ww * 128 + t];
            dsum.x += v.x; dsum.y += v.y; dsum.z += v.z; dsum.w += v.w;
        }
        const float  s  = ALPHA / (float)(cnt + 1);
        const float4 cc = crow[t];
        float4 nc;
        nc.x = cc.x - dsum.x * s;
        nc.y = cc.y - dsum.y * s;
        nc.z = cc.z - dsum.z * s;
        nc.w = cc.w - dsum.w * s;
        newc[c * 128 + t] = nc;
    }

    if (t == 0) g_cnt[c] = 0;   // leave scratch zeroed for the next replay
}

extern "C" void kernel_launch(void* const* d_in, const int* in_sizes, int n_in,
                              void* d_out, int out_size) {
    const float* features = (const float*)d_in[0];   // 16384*512
    const float* centers  = (const float*)d_in[1];   // 1024*512
    const int*   labels   = (const int*)  d_in[2];   // 16384

    float* out        = (float*)d_out;
    float* result     = out;            // [16384]
    float* newcenters = out + BATCH;    // [1024*512], 64KB offset -> 16B aligned

    cl_hist_scatter<<<BATCH / 256, 256>>>(labels);

    cudaFuncSetAttribute(cl_main,
                         cudaFuncAttributeMaxDynamicSharedMemorySize,
                         DSMEM_BYTES);

    cl_main<<<NUM_CLASSES, 256, DSMEM_BYTES>>>(
        features,
        (const float4*)centers,
        result,
        (float4*)newcenters);
}

// round 12
// speedup vs baseline: 1.2369x; 1.2369x over previous
#include <cuda_runtime.h>
#include <cstdint>

#define NUM_CLASSES 1024
#define FEAT_DIM    512
#define BATCH       16384
#define ALPHA       0.5f
#define MAXC        192   // slot capacity per class (Binomial mean 16; max ~40)

// Scratch (allocation-free rule): zero-init at module load; cl_update re-zeros
// g_cnt in its epilogue so every graph replay sees zeros.
__device__ int g_cnt[NUM_CLASSES];
__device__ int g_slot[NUM_CLASSES * MAXC];

// Kernel A: WARP PER SAMPLE (grid 2048 x 256 = 16384 warps). Streams the
// feature matrix linearly (each warp reads its sample's 2KB row as 4
// independent float4 loads/lane), gathers the class center row (centers are
// 2MB -> L2-resident), shuffle-reduces the squared distance, and fuses the
// histogram + slot scatter (lane 0). Embarrassingly parallel -> DRAM-bound.
__global__ __launch_bounds__(256) void cl_result(
    const float4* __restrict__ feat,     // [BATCH][128] float4
    const float4* __restrict__ centers,  // [C][128] float4
    const int*    __restrict__ labels,   // [BATCH]
    float*        __restrict__ result)   // [BATCH]
{
    const int t    = threadIdx.x;
    const int lane = t & 31;
    const int w    = t >> 5;
    const int i    = blockIdx.x * 8 + w;          // sample id

    // Coalesced label read: lanes 0..7 fetch the block's 8 labels.
    int lbl = 0;
    if (lane < 8) lbl = labels[blockIdx.x * 8 + lane];
    const int c = __shfl_sync(0xffffffffu, lbl, w & 7);

    // Fused histogram + slot scatter (fire-and-forget off critical path).
    if (lane == 0) {
        int p = atomicAdd(&g_cnt[c], 1);
        if (p < MAXC) g_slot[c * MAXC + p] = i;
    }

    // Feature row: 4 independent float4 loads per lane (linear, coalesced).
    const float4* frow = feat + (size_t)i * 128;
    float4 f[4];
    #pragma unroll
    for (int q = 0; q < 4; q++) f[q] = frow[lane + 32 * q];

    // Center row gather (L2 hit after warmup).
    const float4* crow = centers + (size_t)c * 128;
    float ss = 0.f;
    #pragma unroll
    for (int q = 0; q < 4; q++) {
        float4 cc = crow[lane + 32 * q];
        float dx = f[q].x - cc.x;
        float dy = f[q].y - cc.y;
        float dz = f[q].z - cc.z;
        float dw = f[q].w - cc.w;
        ss += dx * dx + dy * dy + dz * dz + dw * dw;
    }
    #pragma unroll
    for (int o = 16; o; o >>= 1)
        ss += __shfl_xor_sync(0xffffffffu, ss, o);
    if (lane == 0) result[i] = ss;
}

// Kernel B: one block per class, 4 warps. Runs after cl_result, so the whole
// feature matrix (32MB) is L2-hot -> the gather loop is short-latency. Warp w
// owns samples j = w + 4m; its slot indices are preloaded in one LDG (lane m
// holds sample m's index) and broadcast by shuffle. Depth-1 register pipeline.
// No per-sample output: pure delta accumulation, one smem combine, newc write.
__global__ __launch_bounds__(128) void cl_update(
    const float4* __restrict__ feat,     // [BATCH][128] float4
    const float4* __restrict__ centers,  // [C][128] float4
    float4*       __restrict__ newc)     // [C][128] float4
{
    const int c    = blockIdx.x;
    const int t    = threadIdx.x;
    const int lane = t & 31;
    const int w    = t >> 5;

    __shared__ float4 sdelta[4][128];

    const int cnt = g_cnt[c];
    const int n   = cnt < MAXC ? cnt : MAXC;

    // Warp w: samples j = w + 4m, m = 0..nws-1 (nws <= 48/4 in practice).
    const int nws = (n > w) ? ((n - w + 3) >> 2) : 0;

    const int* slot = g_slot + c * MAXC;
    int myidx = 0;
    if (lane < nws) myidx = slot[w + 4 * lane];   // one coalesced LDG

    const float4* crow = centers + (size_t)c * 128;
    float4 ctr[4];
    #pragma unroll
    for (int k = 0; k < 4; k++) ctr[k] = crow[lane + 32 * k];

    float4 dl[4];
    #pragma unroll
    for (int k = 0; k < 4; k++) dl[k] = make_float4(0.f, 0.f, 0.f, 0.f);

    float4 f_cur[4];
    if (nws > 0) {
        const int b0 = __shfl_sync(0xffffffffu, myidx, 0);
        const float4* frow = feat + (size_t)b0 * 128;
        #pragma unroll
        for (int q = 0; q < 4; q++) f_cur[q] = frow[lane + 32 * q];
    }

    for (int m = 0; m < nws; m++) {
        float4 f_nxt[4];
        if (m + 1 < nws) {
            const int bn = __shfl_sync(0xffffffffu, myidx, m + 1);
            const float4* frow = feat + (size_t)bn * 128;
            #pragma unroll
            for (int q = 0; q < 4; q++) f_nxt[q] = frow[lane + 32 * q];
        }
        #pragma unroll
        for (int q = 0; q < 4; q++) {
            dl[q].x += ctr[q].x - f_cur[q].x;
            dl[q].y += ctr[q].y - f_cur[q].y;
            dl[q].z += ctr[q].z - f_cur[q].z;
            dl[q].w += ctr[q].w - f_cur[q].w;
        }
        if (m + 1 < nws) {
            #pragma unroll
            for (int q = 0; q < 4; q++) f_cur[q] = f_nxt[q];
        }
    }

    // Cross-warp combine (one barrier total).
    #pragma unroll
    for (int k = 0; k < 4; k++) sdelta[w][lane + 32 * k] = dl[k];
    __syncthreads();

    float4 dsum = sdelta[0][t];
    #pragma unroll
    for (int ww = 1; ww < 4; ww++) {
        float4 v = sdelta[ww][t];
        dsum.x += v.x; dsum.y += v.y; dsum.z += v.z; dsum.w += v.w;
    }

    const float  s  = ALPHA / (float)(cnt + 1);
    const float4 cc = crow[t];               // L1/L2 hit
    float4 nc;
    nc.x = cc.x - dsum.x * s;
    nc.y = cc.y - dsum.y * s;
    nc.z = cc.z - dsum.z * s;
    nc.w = cc.w - dsum.w * s;
    newc[c * 128 + t] = nc;

    if (t == 0) g_cnt[c] = 0;   // leave scratch zeroed for the next replay
}

extern "C" void kernel_launch(void* const* d_in, const int* in_sizes, int n_in,
                              void* d_out, int out_size) {
    const float* features = (const float*)d_in[0];   // 16384*512
    const float* centers  = (const float*)d_in[1];   // 1024*512
    const int*   labels   = (const int*)  d_in[2];   // 16384

    float* out        = (float*)d_out;
    float* result     = out;            // [16384]
    float* newcenters = out + BATCH;    // [1024*512], 64KB offset -> 16B aligned

    cl_result<<<BATCH / 8, 256>>>(
        (const float4*)features,
        (const float4*)centers,
        labels,
        result);

    cl_update<<<NUM_CLASSES, 128>>>(
        (const float4*)features,
        (const float4*)centers,
        (float4*)newcenters);
}

// round 15
// speedup vs baseline: 1.4320x; 1.1577x over previous
#include <cuda_runtime.h>
#include <cstdint>

#define NUM_CLASSES 1024
#define FEAT_DIM    512
#define BATCH       16384
#define ALPHA       0.5f
#define MAXC        192   // slot capacity per class (Binomial mean 16; max ~45)

// Scratch (allocation-free rule): zero-init at module load; cl_main re-zeros
// g_cnt in its epilogue so every graph replay sees zeros.
__device__ int g_cnt[NUM_CLASSES];
__device__ int g_slot[NUM_CLASSES * MAXC];

// Kernel 1: histogram + scatter sample indices into per-class slots.
__global__ __launch_bounds__(256) void cl_hist_scatter(const int* __restrict__ labels) {
    int i = blockIdx.x * blockDim.x + threadIdx.x;
    if (i < BATCH) {
        int c = labels[i];
        int p = atomicAdd(&g_cnt[c], 1);
        if (p < MAXC) g_slot[c * MAXC + p] = i;
    }
}

// Kernel 2: one block per class, 8 warps, single pass over features.
// Per phase (32 samples), warp w owns samples base+4w..base+4w+3 and issues
// ALL 16 LDG.128 in straight-line unrolled code BEFORE any consumption —
// front-batched MLP=16 per warp, nothing for ptxas to sink. Per-sample
// squared distance via warp shuffle; delta in registers; one smem combine.
__global__ __launch_bounds__(256) void cl_main(
    const float4* __restrict__ feat,     // [BATCH][128] float4
    const float4* __restrict__ centers,  // [C][128] float4
    float*        __restrict__ result,   // [BATCH]
    float4*       __restrict__ newc)     // [C][128] float4
{
    const int c    = blockIdx.x;
    const int t    = threadIdx.x;
    const int lane = t & 31;
    const int w    = t >> 5;

    __shared__ float4 sdelta[8][128];    // 16KB

    const int cnt = g_cnt[c];
    const int n   = cnt < MAXC ? cnt : MAXC;

    const int*    slot = g_slot + c * MAXC;
    const float4* crow = centers + (size_t)c * 128;

    float4 ctr[4];
    #pragma unroll
    for (int k = 0; k < 4; k++) ctr[k] = crow[lane + 32 * k];

    float4 dl[4];
    #pragma unroll
    for (int k = 0; k < 4; k++) dl[k] = make_float4(0.f, 0.f, 0.f, 0.f);

    for (int base = 0; base < n; base += 32) {
        const int rem = n - base;                 // samples this phase (<=32 used)
        const int mph = rem < 32 ? rem : 32;

        // One coalesced slot load for the phase; lane j holds sample base+j.
        int idx = 0;
        if (lane < mph) idx = slot[base + lane];

        // This warp's 4 samples: j = 4w + u (u = 0..3), valid if < mph.
        int   bs[4];
        bool  v[4];
        #pragma unroll
        for (int u = 0; u < 4; u++) {
            v[u]  = (4 * w + u) < mph;
            bs[u] = __shfl_sync(0xffffffffu, idx, (4 * w + u) & 31);
        }

        // ---- FRONT-BATCHED LOADS: all 16 LDG.128 before any use ----
        float4 f[4][4];
        #pragma unroll
        for (int u = 0; u < 4; u++) {
            const float4* frow = feat + (size_t)bs[u] * 128;
            #pragma unroll
            for (int q = 0; q < 4; q++)
                f[u][q] = v[u] ? frow[lane + 32 * q]
                               : make_float4(0.f, 0.f, 0.f, 0.f);
        }

        // ---- CONSUME ----
        #pragma unroll
        for (int u = 0; u < 4; u++) {
            float ss = 0.f;
            #pragma unroll
            for (int q = 0; q < 4; q++) {
                float dx = ctr[q].x - f[u][q].x;
                float dy = ctr[q].y - f[u][q].y;
                float dz = ctr[q].z - f[u][q].z;
                float dw = ctr[q].w - f[u][q].w;
                if (v[u]) {
                    dl[q].x += dx; dl[q].y += dy;
                    dl[q].z += dz; dl[q].w += dw;
                }
                ss += dx * dx + dy * dy + dz * dz + dw * dw;
            }
            #pragma unroll
            for (int o = 16; o; o >>= 1)
                ss += __shfl_xor_sync(0xffffffffu, ss, o);
            if (v[u] && lane == 0) result[bs[u]] = ss;
        }
    }

    // Cross-warp delta combine (one barrier).
    #pragma unroll
    for (int k = 0; k < 4; k++) sdelta[w][lane + 32 * k] = dl[k];
    __syncthreads();

    if (t < 128) {
        float4 dsum = sdelta[0][t];
        #pragma unroll
        for (int ww = 1; ww < 8; ww++) {
            float4 vv = sdelta[ww][t];
            dsum.x += vv.x; dsum.y += vv.y; dsum.z += vv.z; dsum.w += vv.w;
        }
        const float  s  = ALPHA / (float)(cnt + 1);
        const float4 cc = crow[t];               // cache hit
        float4 nc;
        nc.x = cc.x - dsum.x * s;
        nc.y = cc.y - dsum.y * s;
        nc.z = cc.z - dsum.z * s;
        nc.w = cc.w - dsum.w * s;
        newc[c * 128 + t] = nc;
    }

    if (t == 0) g_cnt[c] = 0;   // leave scratch zeroed for the next replay
}

extern "C" void kernel_launch(void* const* d_in, const int* in_sizes, int n_in,
                              void* d_out, int out_size) {
    const float* features = (const float*)d_in[0];   // 16384*512
    const float* centers  = (const float*)d_in[1];   // 1024*512
    const int*   labels   = (const int*)  d_in[2];   // 16384

    float* out        = (float*)d_out;
    float* result     = out;            // [16384]
    float* newcenters = out + BATCH;    // [1024*512], 64KB offset -> 16B aligned

    cl_hist_scatter<<<BATCH / 256, 256>>>(labels);

    cl_main<<<NUM_CLASSES, 256>>>(
        (const float4*)features,
        (const float4*)centers,
        result,
        (float4*)newcenters);
}